// round 15
// baseline (speedup 1.0000x reference)
#include <cuda_runtime.h>

// Model_76811195122407: 3-layer LIF SNN
// L1 (K=128): strided-4 slices (k mod 4), combine A=(c0+c1)+(c2+c3)
// L2/L3 (K=100): LLVM VF4-IC2 + scalar tail:
//   main 12 iters over chunk pairs (even->v0, odd->v1), u=v0+v1 lanewise,
//   h=(u0+u1)+(u2+u3), then scalar fma tail k=96..99 ascending.
// LIF: m = fsub(fma(0.9, m, cur), reset*0.5)

#define Tn   50
#define Bn   16384
#define DIN  128
#define Hn   100
#define HPAD 104
#define DOUT 128
#define BETA 0.9f
#define THR  0.5f

#define BB   32
#define NPT  13
#define NPTO 16

#define KC_IN (DIN / 4)   // 32
#define KC_H  (HPAD / 4)  // 26 (25 real + 1 zero pad)

#define W1_F (HPAD * DIN)
#define W2_F (HPAD * HPAD)
#define W3_F (DOUT * HPAD)
#define XS_F (DIN * BB)
#define S1_F (HPAD * BB)
#define S2_F (HPAD * BB)
#define SMEM_FLOATS (W1_F + W2_F + W3_F + XS_F + S1_F + S2_F)

extern __shared__ float smem[];

__device__ __forceinline__ void lif_update(float& m, float c, float& spk)
{
    float r  = (m > THR) ? THR : 0.f;
    float t  = __fmaf_rn(BETA, m, c);
    m = __fsub_rn(t, r);
    spk = (m > THR) ? 1.f : 0.f;
}

// L1: strided-4 slices (k mod 4), sequential chains, combine A
__device__ __forceinline__ float dot_strided4(const float4* __restrict__ w4,
                                              const float4* __restrict__ a4,
                                              int l, int KC)
{
    float c0 = 0.f, c1 = 0.f, c2 = 0.f, c3 = 0.f;
#pragma unroll
    for (int kc = 0; kc < KC; kc++) {
        float4 av = a4[kc * BB + l];
        float4 w  = w4[kc];
        c0 = __fmaf_rn(w.x, av.x, c0);
        c1 = __fmaf_rn(w.y, av.y, c1);
        c2 = __fmaf_rn(w.z, av.z, c2);
        c3 = __fmaf_rn(w.w, av.w, c3);
    }
    return __fadd_rn(__fadd_rn(c0, c1), __fadd_rn(c2, c3));
}

// K=100: IC2 main (12 pairs, 96 elems), u=v0+v1, combine A, scalar tail 96..99
__device__ __forceinline__ float dot_ic2_stail(const float4* __restrict__ w4,
                                               const float4* __restrict__ a4,
                                               int l)
{
    float v00=0.f,v01=0.f,v02=0.f,v03=0.f;
    float v10=0.f,v11=0.f,v12=0.f,v13=0.f;
#pragma unroll
    for (int p = 0; p < 12; p++) {
        float4 a0 = a4[(2*p)   * BB + l];
        float4 a1 = a4[(2*p+1) * BB + l];
        float4 w0 = w4[2*p];
        float4 w1 = w4[2*p+1];
        v00 = __fmaf_rn(w0.x, a0.x, v00);
        v01 = __fmaf_rn(w0.y, a0.y, v01);
        v02 = __fmaf_rn(w0.z, a0.z, v02);
        v03 = __fmaf_rn(w0.w, a0.w, v03);
        v10 = __fmaf_rn(w1.x, a1.x, v10);
        v11 = __fmaf_rn(w1.y, a1.y, v11);
        v12 = __fmaf_rn(w1.z, a1.z, v12);
        v13 = __fmaf_rn(w1.w, a1.w, v13);
    }
    float u0 = __fadd_rn(v00, v10);
    float u1 = __fadd_rn(v01, v11);
    float u2 = __fadd_rn(v02, v12);
    float u3 = __fadd_rn(v03, v13);
    float h  = __fadd_rn(__fadd_rn(u0, u1), __fadd_rn(u2, u3));
    // scalar tail: k = 96..99 ascending (chunk 24)
    float4 at = a4[24 * BB + l];
    float4 wt = w4[24];
    h = __fmaf_rn(wt.x, at.x, h);
    h = __fmaf_rn(wt.y, at.y, h);
    h = __fmaf_rn(wt.z, at.z, h);
    h = __fmaf_rn(wt.w, at.w, h);
    return h;
}

__global__ void __launch_bounds__(256, 1) snn_lif3_kernel(
    const float* __restrict__ x,
    const float* __restrict__ W1,
    const float* __restrict__ W2,
    const float* __restrict__ W3,
    float* __restrict__ out)
{
    float* w1s = smem;
    float* w2s = w1s + W1_F;
    float* w3s = w2s + W2_F;
    float* xs  = w3s + W3_F;
    float* s1  = xs + XS_F;
    float* s2  = s1 + S1_F;

    const int tid = threadIdx.x;
    const int l   = tid & 31;
    const int g   = tid >> 5;

    for (int i = tid; i < W1_F + W2_F + W3_F; i += 256) w1s[i] = 0.f;
    __syncthreads();
    for (int i = tid; i < Hn * DIN; i += 256) w1s[i] = W1[i];
    for (int i = tid; i < Hn * Hn; i += 256) {
        int n = i / Hn, k = i - n * Hn;
        w2s[n * HPAD + k] = W2[i];
    }
    for (int i = tid; i < DOUT * Hn; i += 256) {
        int n = i / Hn, k = i - n * Hn;
        w3s[n * HPAD + k] = W3[i];
    }
    __syncthreads();

    const float4* xs4  = (const float4*)xs;
    const float4* s14  = (const float4*)s1;
    const float4* s24  = (const float4*)s2;
    const float4* w1_4 = (const float4*)w1s;
    const float4* w2_4 = (const float4*)w2s;
    const float4* w3_4 = (const float4*)w3s;

    const int n0  = g * NPT;
    const int n0o = g * NPTO;
    const int b   = blockIdx.x * BB + l;

    float m1[NPT], m2[NPT], m3[NPTO];
#pragma unroll
    for (int i = 0; i < NPT; i++)  { m1[i] = 0.f; m2[i] = 0.f; }
#pragma unroll
    for (int i = 0; i < NPTO; i++) { m3[i] = 0.f; }

    const size_t MEMOFF = (size_t)Tn * Bn * DOUT;

    for (int t = 0; t < Tn; t++) {
        const float4* gx =
            (const float4*)(x + ((size_t)t * Bn + (size_t)blockIdx.x * BB) * DIN);
#pragma unroll
        for (int j = 0; j < 4; j++) {
            int idx = tid + j * 256;
            float4 v = gx[idx];
            int row = idx >> 5;
            int kc  = idx & 31;
            ((float4*)xs)[kc * BB + row] = v;
        }
        __syncthreads();

        // ===== layer 1: K=128, strided-4, combine A =====
#pragma unroll
        for (int i = 0; i < NPT; i++) {
            float c = dot_strided4(&w1_4[(n0 + i) * KC_IN], xs4, l, KC_IN);
            float s;
            lif_update(m1[i], c, s);
            int n = n0 + i;
            s1[(n >> 2) * (BB * 4) + l * 4 + (n & 3)] = s;
        }
        __syncthreads();

        // ===== layer 2: K=100, IC2 + scalar tail =====
#pragma unroll
        for (int i = 0; i < NPT; i++) {
            float c = dot_ic2_stail(&w2_4[(n0 + i) * KC_H], s14, l);
            float s;
            lif_update(m2[i], c, s);
            int n = n0 + i;
            s2[(n >> 2) * (BB * 4) + l * 4 + (n & 3)] = s;
        }
        __syncthreads();

        // ===== layer 3: K=100, IC2 + scalar tail =====
        {
            size_t obase = ((size_t)t * Bn + b) * DOUT + n0o;
#pragma unroll
            for (int i = 0; i < NPTO; i += 4) {
                float4 sv4, mv4;
                float c0 = dot_ic2_stail(&w3_4[(n0o + i + 0) * KC_H], s24, l);
                float c1 = dot_ic2_stail(&w3_4[(n0o + i + 1) * KC_H], s24, l);
                float c2 = dot_ic2_stail(&w3_4[(n0o + i + 2) * KC_H], s24, l);
                float c3 = dot_ic2_stail(&w3_4[(n0o + i + 3) * KC_H], s24, l);
                lif_update(m3[i],   c0, sv4.x); mv4.x = m3[i];
                lif_update(m3[i+1], c1, sv4.y); mv4.y = m3[i+1];
                lif_update(m3[i+2], c2, sv4.z); mv4.z = m3[i+2];
                lif_update(m3[i+3], c3, sv4.w); mv4.w = m3[i+3];
                *(float4*)(out + obase + i)          = sv4;
                *(float4*)(out + MEMOFF + obase + i) = mv4;
            }
        }
        __syncthreads();
    }
}

extern "C" void kernel_launch(void* const* d_in, const int* in_sizes, int n_in,
                              void* d_out, int out_size)
{
    const float* x  = (const float*)d_in[0];
    const float* W1 = (const float*)d_in[1];
    const float* W2 = (const float*)d_in[2];
    const float* W3 = (const float*)d_in[3];
    float* out = (float*)d_out;

    size_t smem_bytes = (size_t)SMEM_FLOATS * sizeof(float);
    cudaFuncSetAttribute(snn_lif3_kernel,
                         cudaFuncAttributeMaxDynamicSharedMemorySize,
                         (int)smem_bytes);

    dim3 grid(Bn / BB);
    dim3 block(256);
    snn_lif3_kernel<<<grid, block, smem_bytes>>>(x, W1, W2, W3, out);
}